// round 9
// baseline (speedup 1.0000x reference)
#include <cuda_runtime.h>
#include <cuda_fp16.h>
#include <cstdint>

#define N_NODES 50000
#define N_EDGES 800000
#define D_IN    256
#define D_OUT   128

#define SCAN_BLOCKS ((N_NODES + 1023) / 1024)   // 49

// ---------------- scratch (no allocations allowed) ----------------
__device__ int    g_deg   [N_NODES];
__device__ float  g_dinv  [N_NODES];
__device__ int    g_rowptr[N_NODES + 1];
__device__ int    g_cursor[N_NODES];
__device__ int    g_col   [N_EDGES];
__device__ int    g_bsum  [64];
__device__ __align__(16) __half g_h[(size_t)N_NODES * D_OUT];   // 12.8 MB, pre-scaled

// ---------------- streams/events (created before capture) ----------------
static cudaStream_t g_s2;
static cudaEvent_t  g_evFork, g_evDinv, g_evJoin;
static struct StreamInit {
    StreamInit() {
        cudaStreamCreateWithFlags(&g_s2, cudaStreamNonBlocking);
        cudaEventCreateWithFlags(&g_evFork, cudaEventDisableTiming);
        cudaEventCreateWithFlags(&g_evDinv, cudaEventDisableTiming);
        cudaEventCreateWithFlags(&g_evJoin, cudaEventDisableTiming);
    }
} g_streamInit;

// ---------------- 1. histogram of dst ----------------
__global__ void k_count(const int* __restrict__ ei, int* deg) {
    int e = blockIdx.x * blockDim.x + threadIdx.x;
    if (e < N_EDGES) atomicAdd(&deg[ei[N_EDGES + e]], 1);
}

// ---------------- 2. fused scan: partials + decoupled lookback + write ------
// 49 blocks, all co-resident (wave 1) -> spin on predecessors is safe.
__global__ __launch_bounds__(256) void k_scanf(const int* __restrict__ deg,
                                               int* bsum,     // zeroed, publish s+1
                                               int* __restrict__ rowptr,
                                               int* __restrict__ cursor,
                                               float* __restrict__ dinv) {
    __shared__ int ws[8];        // warp inclusive totals
    __shared__ int woff[8];      // warp exclusive offsets
    __shared__ int pred[64];     // predecessor sums
    __shared__ int boffs;

    int b = blockIdx.x, t = threadIdx.x;
    int lane = t & 31, w = t >> 5;
    int base = b * 1024 + t * 4;

    int d[4];
    int s = 0;
#pragma unroll
    for (int q = 0; q < 4; q++) {
        int i = base + q;
        d[q] = (i < N_NODES) ? deg[i] : 0;
        s += d[q];
    }
    // warp inclusive scan
    int inc = s;
    for (int o = 1; o < 32; o <<= 1) {
        int v = __shfl_up_sync(0xffffffffu, inc, o);
        if (lane >= o) inc += v;
    }
    if (lane == 31) ws[w] = inc;
    if (t < 64) pred[t] = 0;
    __syncthreads();

    // warp offsets + block total
    if (t < 8) {
        int v = ws[t];
        int p = v;
        for (int o = 1; o < 8; o <<= 1) {
            int u = __shfl_up_sync(0xffu, p, o);
            if (t >= o) p += u;
        }
        woff[t] = p - v;               // exclusive
        if (t == 7) {
            // publish block total (inclusive p of last warp)
            __threadfence();
            atomicExch(&bsum[b], p + 1);
        }
    }
    // lookback: thread t < b polls predecessor t
    if (t < b) {
        int v;
        do { v = *((volatile int*)&bsum[t]); } while (v == 0);
        pred[t] = v - 1;
    }
    __syncthreads();
    if (t < 32) {
        int ss = pred[t] + pred[t + 32];
        for (int o = 16; o; o >>= 1) ss += __shfl_down_sync(0xffffffffu, ss, o);
        if (t == 0) boffs = ss;
    }
    __syncthreads();

    int off = boffs + woff[w] + (inc - s);
#pragma unroll
    for (int q = 0; q < 4; q++) {
        int i = base + q;
        if (i < N_NODES) {
            rowptr[i] = off;
            cursor[i] = off;
            dinv[i]   = rsqrtf((float)d[q] + 1.0f);   // +1 = self loop
            off += d[q];
        }
    }
    if (b == 0 && t == 0) rowptr[N_NODES] = N_EDGES;
}

// ---------------- 3. bucket fill: col only ----------------
__global__ void k_fill(const int* __restrict__ ei, int* __restrict__ cursor,
                       int* __restrict__ col) {
    int e = blockIdx.x * blockDim.x + threadIdx.x;
    if (e < N_EDGES) {
        int src = ei[e];
        int dst = ei[N_EDGES + e];
        int pos = atomicAdd(&cursor[dst], 1);
        col[pos] = src;
    }
}

// ---------------- 4. GEMM h' = dinv * (x @ W), fp16 mma.sync ----------------
#define WP_HALF2   (128 * 136)
#define A_STRIDE   24
#define A_STAGE    (128 * A_STRIDE)
#define GEMM_SMEM  (WP_HALF2 * 4 + 2 * A_STAGE * 2)   // 81920 B

__global__ __launch_bounds__(256) void k_gemm16(const float* __restrict__ X,
                                                const float* __restrict__ W,
                                                const float* __restrict__ dinv,
                                                __half* __restrict__ H) {
    extern __shared__ char smem_raw[];
    half2*  Wp = (half2*)smem_raw;
    __half* As = (__half*)(smem_raw + WP_HALF2 * 4);

    const int tid  = threadIdx.x;
    const int warp = tid >> 5;
    const int lane = tid & 31;
    const int g    = lane >> 2;
    const int tig  = lane & 3;
    const int m0   = blockIdx.x * 128;

    const float4* X4 = (const float4*)X;
    const float4* W4 = (const float4*)W;

#pragma unroll
    for (int i = 0; i < 16; i++) {
        int item = tid + i * 256;
        int kp   = item >> 5;
        int n4   = item & 31;
        float4 a = W4[(size_t)(2 * kp) * 32 + n4];
        float4 c = W4[(size_t)(2 * kp + 1) * 32 + n4];
        half2 h0 = __floats2half2_rn(a.x, c.x);
        half2 h1 = __floats2half2_rn(a.y, c.y);
        half2 h2 = __floats2half2_rn(a.z, c.z);
        half2 h3 = __floats2half2_rn(a.w, c.w);
        half2* dst = &Wp[kp * 136 + n4 * 4];
        uint4 pack;
        pack.x = *(unsigned*)&h0; pack.y = *(unsigned*)&h1;
        pack.z = *(unsigned*)&h2; pack.w = *(unsigned*)&h3;
        *(uint4*)dst = pack;
    }

#pragma unroll
    for (int p = 0; p < 2; p++) {
        int idx = tid + p * 256;
        int r   = idx >> 2;
        int c4  = idx & 3;
        int gr  = m0 + r;
        float4 v = make_float4(0.f, 0.f, 0.f, 0.f);
        if (gr < N_NODES) v = X4[(size_t)gr * 64 + c4];
        half2 h01 = __floats2half2_rn(v.x, v.y);
        half2 h23 = __floats2half2_rn(v.z, v.w);
        uint2 u; u.x = *(unsigned*)&h01; u.y = *(unsigned*)&h23;
        *(uint2*)(As + r * A_STRIDE + c4 * 4) = u;
    }
    __syncthreads();

    float acc[16][4];
#pragma unroll
    for (int nt = 0; nt < 16; nt++)
#pragma unroll
        for (int j = 0; j < 4; j++) acc[nt][j] = 0.0f;

    const int rowA = warp * 16 + g;

    int buf = 0;
#pragma unroll 1
    for (int ks = 0; ks < 16; ks++) {
        float4 pre[2];
        if (ks + 1 < 16) {
            int k0n = (ks + 1) * 16;
#pragma unroll
            for (int p = 0; p < 2; p++) {
                int idx = tid + p * 256;
                int r   = idx >> 2;
                int c4  = idx & 3;
                int gr  = m0 + r;
                pre[p] = make_float4(0.f, 0.f, 0.f, 0.f);
                if (gr < N_NODES) pre[p] = X4[(size_t)gr * 64 + (k0n >> 2) + c4];
            }
        }

        const __half* Ab = As + buf * A_STAGE;
        unsigned a0 = *(const unsigned*)(Ab + rowA * A_STRIDE + 2 * tig);
        unsigned a1 = *(const unsigned*)(Ab + (rowA + 8) * A_STRIDE + 2 * tig);
        unsigned a2 = *(const unsigned*)(Ab + rowA * A_STRIDE + 2 * tig + 8);
        unsigned a3 = *(const unsigned*)(Ab + (rowA + 8) * A_STRIDE + 2 * tig + 8);

        int k0h = ks * 8;
#pragma unroll
        for (int nt = 0; nt < 16; nt++) {
            int n0 = nt * 8;
            unsigned b0 = *(const unsigned*)&Wp[(k0h + tig) * 136 + n0 + g];
            unsigned b1 = *(const unsigned*)&Wp[(k0h + 4 + tig) * 136 + n0 + g];
            asm volatile(
                "mma.sync.aligned.m16n8k16.row.col.f32.f16.f16.f32 "
                "{%0,%1,%2,%3}, {%4,%5,%6,%7}, {%8,%9}, {%0,%1,%2,%3};\n"
                : "+f"(acc[nt][0]), "+f"(acc[nt][1]),
                  "+f"(acc[nt][2]), "+f"(acc[nt][3])
                : "r"(a0), "r"(a1), "r"(a2), "r"(a3), "r"(b0), "r"(b1));
        }

        if (ks + 1 < 16) {
            int nbuf = buf ^ 1;
#pragma unroll
            for (int p = 0; p < 2; p++) {
                int idx = tid + p * 256;
                int r   = idx >> 2;
                int c4  = idx & 3;
                half2 h01 = __floats2half2_rn(pre[p].x, pre[p].y);
                half2 h23 = __floats2half2_rn(pre[p].z, pre[p].w);
                uint2 u; u.x = *(unsigned*)&h01; u.y = *(unsigned*)&h23;
                *(uint2*)(As + nbuf * A_STAGE + r * A_STRIDE + c4 * 4) = u;
            }
            __syncthreads();
            buf = nbuf;
        }
    }

    // ---- epilogue: scale by dinv[row], convert to fp16
    int r0 = m0 + rowA;
    float d0 = (r0     < N_NODES) ? dinv[r0]     : 0.0f;
    float d1 = (r0 + 8 < N_NODES) ? dinv[r0 + 8] : 0.0f;
#pragma unroll
    for (int nt = 0; nt < 16; nt++) {
        int col = nt * 8 + 2 * tig;
        half2 lo = __floats2half2_rn(acc[nt][0] * d0, acc[nt][1] * d0);
        half2 hi = __floats2half2_rn(acc[nt][2] * d1, acc[nt][3] * d1);
        if (r0 < N_NODES)
            *(unsigned*)(H + (size_t)r0 * 128 + col) = *(unsigned*)&lo;
        if (r0 + 8 < N_NODES)
            *(unsigned*)(H + (size_t)(r0 + 8) * 128 + col) = *(unsigned*)&hi;
    }
}

// ---------------- 5. gather: out = dinv_i * (sum h'[src] + h'[i]) + b, PReLU
__global__ __launch_bounds__(256) void k_gather(const int* __restrict__ rowptr,
                                                const int* __restrict__ col,
                                                const float* __restrict__ dinv,
                                                const __half* __restrict__ H,
                                                const float* __restrict__ b,
                                                const float* __restrict__ pa,
                                                float* __restrict__ out) {
    int node = blockIdx.x * 8 + (threadIdx.x >> 5);
    int lane = threadIdx.x & 31;
    if (node >= N_NODES) return;

    const uint2* H2 = (const uint2*)H;
    float di = dinv[node];

    // self-loop: h'[node]
    uint2 sraw = H2[(size_t)node * 32 + lane];
    float2 s01 = __half22float2(*reinterpret_cast<const __half2*>(&sraw.x));
    float2 s23 = __half22float2(*reinterpret_cast<const __half2*>(&sraw.y));
    float4 acc = make_float4(s01.x, s01.y, s23.x, s23.y);

    int r0 = rowptr[node];
    int r1 = rowptr[node + 1];

    for (int base = r0; base < r1; base += 32) {
        int e    = base + lane;
        int srcL = (e < r1) ? col[e] : 0;
        int cnt  = min(32, r1 - base);

        int j = 0;
        for (; j + 8 <= cnt; j += 8) {
            uint2 v[8];
#pragma unroll
            for (int t = 0; t < 8; t++) {
                int src = __shfl_sync(0xffffffffu, srcL, j + t);
                v[t]    = H2[(size_t)src * 32 + lane];
            }
#pragma unroll
            for (int t = 0; t < 8; t++) {
                float2 f01 = __half22float2(*reinterpret_cast<const __half2*>(&v[t].x));
                float2 f23 = __half22float2(*reinterpret_cast<const __half2*>(&v[t].y));
                acc.x += f01.x;
                acc.y += f01.y;
                acc.z += f23.x;
                acc.w += f23.y;
            }
        }
        for (; j + 4 <= cnt; j += 4) {
            uint2 v[4];
#pragma unroll
            for (int t = 0; t < 4; t++) {
                int src = __shfl_sync(0xffffffffu, srcL, j + t);
                v[t]    = H2[(size_t)src * 32 + lane];
            }
#pragma unroll
            for (int t = 0; t < 4; t++) {
                float2 f01 = __half22float2(*reinterpret_cast<const __half2*>(&v[t].x));
                float2 f23 = __half22float2(*reinterpret_cast<const __half2*>(&v[t].y));
                acc.x += f01.x;
                acc.y += f01.y;
                acc.z += f23.x;
                acc.w += f23.y;
            }
        }
        for (; j < cnt; j++) {
            int src = __shfl_sync(0xffffffffu, srcL, j);
            uint2 v = H2[(size_t)src * 32 + lane];
            float2 f01 = __half22float2(*reinterpret_cast<const __half2*>(&v.x));
            float2 f23 = __half22float2(*reinterpret_cast<const __half2*>(&v.y));
            acc.x += f01.x;
            acc.y += f01.y;
            acc.z += f23.x;
            acc.w += f23.y;
        }
    }

    float4 bb = ((const float4*)b)[lane];
    float4 aa = ((const float4*)pa)[lane];
    float4 o;
    o.x = acc.x * di + bb.x;
    o.y = acc.y * di + bb.y;
    o.z = acc.z * di + bb.z;
    o.w = acc.w * di + bb.w;
    o.x = o.x > 0.f ? o.x : aa.x * o.x;
    o.y = o.y > 0.f ? o.y : aa.y * o.y;
    o.z = o.z > 0.f ? o.z : aa.z * o.z;
    o.w = o.w > 0.f ? o.w : aa.w * o.w;
    ((float4*)out)[(size_t)node * 32 + lane] = o;
}

// ---------------- launch ----------------
extern "C" void kernel_launch(void* const* d_in, const int* in_sizes, int n_in,
                              void* d_out, int out_size) {
    const float* x  = (const float*)d_in[0];
    const int*   ei = (const int*)d_in[1];     // [2, N_EDGES] int32
    const float* W  = (const float*)d_in[2];
    const float* b  = (const float*)d_in[3];
    const float* pa = (const float*)d_in[4];
    float* out = (float*)d_out;

    int*    deg;    cudaGetSymbolAddress((void**)&deg,    g_deg);
    float*  dinv;   cudaGetSymbolAddress((void**)&dinv,   g_dinv);
    int*    rowptr; cudaGetSymbolAddress((void**)&rowptr, g_rowptr);
    int*    cursor; cudaGetSymbolAddress((void**)&cursor, g_cursor);
    int*    col;    cudaGetSymbolAddress((void**)&col,    g_col);
    int*    bsum;   cudaGetSymbolAddress((void**)&bsum,   g_bsum);
    __half* h;      cudaGetSymbolAddress((void**)&h,      g_h);

    cudaFuncSetAttribute(k_gemm16, cudaFuncAttributeMaxDynamicSharedMemorySize,
                         GEMM_SMEM);

    cudaEventRecord(g_evFork, 0);
    cudaStreamWaitEvent(g_s2, g_evFork, 0);

    cudaMemsetAsync(deg, 0, N_NODES * sizeof(int), g_s2);
    cudaMemsetAsync(bsum, 0, 64 * sizeof(int), g_s2);
    k_count<<<(N_EDGES + 255) / 256, 256, 0, g_s2>>>(ei, deg);
    k_scanf<<<SCAN_BLOCKS, 256, 0, g_s2>>>(deg, bsum, rowptr, cursor, dinv);
    cudaEventRecord(g_evDinv, g_s2);
    k_fill <<<(N_EDGES + 255) / 256, 256, 0, g_s2>>>(ei, cursor, col);
    cudaEventRecord(g_evJoin, g_s2);

    // GEMM needs dinv (epilogue pre-scale); runs concurrent with k_fill
    cudaStreamWaitEvent(0, g_evDinv, 0);
    k_gemm16<<<(N_NODES + 127) / 128, 256, GEMM_SMEM>>>(x, W, dinv, h);

    cudaStreamWaitEvent(0, g_evJoin, 0);
    k_gather<<<(N_NODES + 7) / 8, 256>>>(rowptr, col, dinv, h, b, pa, out);
}

// round 10
// speedup vs baseline: 1.2847x; 1.2847x over previous
#include <cuda_runtime.h>
#include <cuda_fp16.h>
#include <cstdint>

#define N_NODES 50000
#define N_EDGES 800000
#define D_IN    256
#define D_OUT   128

#define SCAN_BLOCKS ((N_NODES + 1023) / 1024)   // 49

// ---------------- scratch (no allocations allowed) ----------------
__device__ int    g_deg   [N_NODES];
__device__ float  g_dinv  [N_NODES];
__device__ int    g_rowptr[N_NODES + 1];
__device__ int    g_cursor[N_NODES];
__device__ int2   g_edge  [N_EDGES];     // {src, __float_as_int(dinv[src])}
__device__ int    g_bsum  [64];
__device__ __align__(16) __half g_h[(size_t)N_NODES * D_OUT];   // 12.8 MB

// ---------------- streams/events (created before capture) ----------------
static cudaStream_t g_s2;
static cudaEvent_t  g_evFork, g_evJoin;
static struct StreamInit {
    StreamInit() {
        cudaStreamCreateWithFlags(&g_s2, cudaStreamNonBlocking);
        cudaEventCreateWithFlags(&g_evFork, cudaEventDisableTiming);
        cudaEventCreateWithFlags(&g_evJoin, cudaEventDisableTiming);
    }
} g_streamInit;

// ---------------- 1. histogram of dst (x4 vectorized) ----------------
__global__ void k_count(const int4* __restrict__ dst4, int* deg) {
    int e = blockIdx.x * blockDim.x + threadIdx.x;
    if (e < N_EDGES / 4) {
        int4 d = dst4[e];
        atomicAdd(&deg[d.x], 1);
        atomicAdd(&deg[d.y], 1);
        atomicAdd(&deg[d.z], 1);
        atomicAdd(&deg[d.w], 1);
    }
}

// ---------------- 2. fused scan: decoupled lookback (49 co-resident blocks) -
__global__ __launch_bounds__(256) void k_scanf(const int* __restrict__ deg,
                                               int* bsum,     // zeroed, publish s+1
                                               int* __restrict__ rowptr,
                                               int* __restrict__ cursor,
                                               float* __restrict__ dinv) {
    __shared__ int ws[8];
    __shared__ int woff[8];
    __shared__ int pred[64];
    __shared__ int boffs;

    int b = blockIdx.x, t = threadIdx.x;
    int lane = t & 31, w = t >> 5;
    int base = b * 1024 + t * 4;

    int d[4];
    int s = 0;
#pragma unroll
    for (int q = 0; q < 4; q++) {
        int i = base + q;
        d[q] = (i < N_NODES) ? deg[i] : 0;
        s += d[q];
    }
    int inc = s;
    for (int o = 1; o < 32; o <<= 1) {
        int v = __shfl_up_sync(0xffffffffu, inc, o);
        if (lane >= o) inc += v;
    }
    if (lane == 31) ws[w] = inc;
    if (t < 64) pred[t] = 0;
    __syncthreads();

    if (t < 8) {
        int v = ws[t];
        int p = v;
        for (int o = 1; o < 8; o <<= 1) {
            int u = __shfl_up_sync(0xffu, p, o);
            if (t >= o) p += u;
        }
        woff[t] = p - v;
        if (t == 7) {
            __threadfence();
            atomicExch(&bsum[b], p + 1);
        }
    }
    if (t < b) {
        int v;
        do { v = *((volatile int*)&bsum[t]); } while (v == 0);
        pred[t] = v - 1;
    }
    __syncthreads();
    if (t < 32) {
        int ss = pred[t] + pred[t + 32];
        for (int o = 16; o; o >>= 1) ss += __shfl_down_sync(0xffffffffu, ss, o);
        if (t == 0) boffs = ss;
    }
    __syncthreads();

    int off = boffs + woff[w] + (inc - s);
#pragma unroll
    for (int q = 0; q < 4; q++) {
        int i = base + q;
        if (i < N_NODES) {
            rowptr[i] = off;
            cursor[i] = off;
            dinv[i]   = rsqrtf((float)d[q] + 1.0f);   // +1 = self loop
            off += d[q];
        }
    }
    if (b == 0 && t == 0) rowptr[N_NODES] = N_EDGES;
}

// ---------------- 3. bucket fill x2: {src, dinv[src]} ----------------
__global__ void k_fill(const int2* __restrict__ src2,
                       const int2* __restrict__ dst2,
                       int* __restrict__ cursor,
                       const float* __restrict__ dinv,
                       int2* __restrict__ edge) {
    int e = blockIdx.x * blockDim.x + threadIdx.x;
    if (e < N_EDGES / 2) {
        int2 s = src2[e];
        int2 d = dst2[e];
        float f0 = dinv[s.x];
        float f1 = dinv[s.y];
        int p0 = atomicAdd(&cursor[d.x], 1);
        edge[p0] = make_int2(s.x, __float_as_int(f0));
        int p1 = atomicAdd(&cursor[d.y], 1);
        edge[p1] = make_int2(s.y, __float_as_int(f1));
    }
}

// ---------------- 4. GEMM h = x @ W, fp16 mma.sync, streaming A+B ----------
// block tile 64x128, 8 warps as 4(m) x 2(n); warp tile m16 n64.
// smem per stage: A 64x16 half (stride 24), B 8 k-pairs x 132 half2. ~20 KB.
#define AS_STRIDE 24
#define AS_STAGE  (64 * AS_STRIDE)      // halves
#define BS_STAGE  (8 * 132)             // half2

__global__ __launch_bounds__(256, 4) void k_gemm16(const float* __restrict__ X,
                                                   const float* __restrict__ W,
                                                   __half* __restrict__ H) {
    __shared__ __half As[2][AS_STAGE];
    __shared__ half2  Bs[2][BS_STAGE];

    const int tid  = threadIdx.x;
    const int warp = tid >> 5;
    const int lane = tid & 31;
    const int g    = lane >> 2;      // 0..7
    const int tig  = lane & 3;       // 0..3
    const int m0   = blockIdx.x * 64;
    const int mrow = (warp >> 1) * 16;   // 0,16,32,48
    const int ncol = (warp & 1) * 64;    // 0 or 64

    const float4* X4 = (const float4*)X;   // row stride 64
    const float4* W4 = (const float4*)W;   // row stride 32

    // per-chunk loader indices
    const int ar  = tid >> 2;        // 0..63  A row
    const int ac4 = tid & 3;         // 0..3   A k-quad (4 floats)
    const int bkp = tid >> 5;        // 0..7   B k-pair row
    const int bn4 = tid & 31;        // 0..31  B float4 col

    // ---- stage 0
    {
        int gr = m0 + ar;
        float4 v = make_float4(0.f, 0.f, 0.f, 0.f);
        if (gr < N_NODES) v = X4[(size_t)gr * 64 + ac4];
        half2 h01 = __floats2half2_rn(v.x, v.y);
        half2 h23 = __floats2half2_rn(v.z, v.w);
        uint2 u; u.x = *(unsigned*)&h01; u.y = *(unsigned*)&h23;
        *(uint2*)(&As[0][ar * AS_STRIDE + ac4 * 4]) = u;

        float4 a = W4[(size_t)(2 * bkp) * 32 + bn4];
        float4 c = W4[(size_t)(2 * bkp + 1) * 32 + bn4];
        half2 p0 = __floats2half2_rn(a.x, c.x);
        half2 p1 = __floats2half2_rn(a.y, c.y);
        half2 p2 = __floats2half2_rn(a.z, c.z);
        half2 p3 = __floats2half2_rn(a.w, c.w);
        uint4 pk;
        pk.x = *(unsigned*)&p0; pk.y = *(unsigned*)&p1;
        pk.z = *(unsigned*)&p2; pk.w = *(unsigned*)&p3;
        *(uint4*)(&Bs[0][bkp * 132 + bn4 * 4]) = pk;
    }
    __syncthreads();

    float acc[8][4];
#pragma unroll
    for (int nt = 0; nt < 8; nt++)
#pragma unroll
        for (int j = 0; j < 4; j++) acc[nt][j] = 0.0f;

    int buf = 0;
#pragma unroll 1
    for (int ks = 0; ks < 16; ks++) {
        // reg-prefetch next chunk
        float4 preA = make_float4(0.f, 0.f, 0.f, 0.f);
        float4 preB0, preB1;
        if (ks + 1 < 16) {
            int k0n = (ks + 1) * 16;
            int gr = m0 + ar;
            if (gr < N_NODES) preA = X4[(size_t)gr * 64 + (k0n >> 2) + ac4];
            preB0 = W4[(size_t)(k0n + 2 * bkp) * 32 + bn4];
            preB1 = W4[(size_t)(k0n + 2 * bkp + 1) * 32 + bn4];
        }

        // A fragment (m16 k16) for this warp
        const __half* Ab = &As[buf][0];
        int r = mrow + g;
        unsigned a0 = *(const unsigned*)(Ab + r * AS_STRIDE + 2 * tig);
        unsigned a1 = *(const unsigned*)(Ab + (r + 8) * AS_STRIDE + 2 * tig);
        unsigned a2 = *(const unsigned*)(Ab + r * AS_STRIDE + 2 * tig + 8);
        unsigned a3 = *(const unsigned*)(Ab + (r + 8) * AS_STRIDE + 2 * tig + 8);

#pragma unroll
        for (int nt = 0; nt < 8; nt++) {
            int n0 = ncol + nt * 8;
            unsigned b0 = *(const unsigned*)&Bs[buf][tig * 132 + n0 + g];
            unsigned b1 = *(const unsigned*)&Bs[buf][(tig + 4) * 132 + n0 + g];
            asm volatile(
                "mma.sync.aligned.m16n8k16.row.col.f32.f16.f16.f32 "
                "{%0,%1,%2,%3}, {%4,%5,%6,%7}, {%8,%9}, {%0,%1,%2,%3};\n"
                : "+f"(acc[nt][0]), "+f"(acc[nt][1]),
                  "+f"(acc[nt][2]), "+f"(acc[nt][3])
                : "r"(a0), "r"(a1), "r"(a2), "r"(a3), "r"(b0), "r"(b1));
        }

        if (ks + 1 < 16) {
            int nbuf = buf ^ 1;
            half2 h01 = __floats2half2_rn(preA.x, preA.y);
            half2 h23 = __floats2half2_rn(preA.z, preA.w);
            uint2 u; u.x = *(unsigned*)&h01; u.y = *(unsigned*)&h23;
            *(uint2*)(&As[nbuf][ar * AS_STRIDE + ac4 * 4]) = u;

            half2 p0 = __floats2half2_rn(preB0.x, preB1.x);
            half2 p1 = __floats2half2_rn(preB0.y, preB1.y);
            half2 p2 = __floats2half2_rn(preB0.z, preB1.z);
            half2 p3 = __floats2half2_rn(preB0.w, preB1.w);
            uint4 pk;
            pk.x = *(unsigned*)&p0; pk.y = *(unsigned*)&p1;
            pk.z = *(unsigned*)&p2; pk.w = *(unsigned*)&p3;
            *(uint4*)(&Bs[nbuf][bkp * 132 + bn4 * 4]) = pk;
            __syncthreads();
            buf = nbuf;
        }
    }

    // ---- epilogue: fp32 acc -> fp16 H (unscaled)
    int r0 = m0 + mrow + g;
#pragma unroll
    for (int nt = 0; nt < 8; nt++) {
        int col = ncol + nt * 8 + 2 * tig;
        half2 lo = __floats2half2_rn(acc[nt][0], acc[nt][1]);
        half2 hi = __floats2half2_rn(acc[nt][2], acc[nt][3]);
        if (r0 < N_NODES)
            *(unsigned*)(H + (size_t)r0 * 128 + col) = *(unsigned*)&lo;
        if (r0 + 8 < N_NODES)
            *(unsigned*)(H + (size_t)(r0 + 8) * 128 + col) = *(unsigned*)&hi;
    }
}

// ---------------- 5. gather (fp16 rows) + self-loop + bias + PReLU ----------
__global__ __launch_bounds__(256) void k_gather(const int* __restrict__ rowptr,
                                                const int2* __restrict__ edge,
                                                const float* __restrict__ dinv,
                                                const __half* __restrict__ H,
                                                const float* __restrict__ b,
                                                const float* __restrict__ pa,
                                                float* __restrict__ out) {
    int node = blockIdx.x * 8 + (threadIdx.x >> 5);
    int lane = threadIdx.x & 31;
    if (node >= N_NODES) return;

    const uint2* H2 = (const uint2*)H;
    float di = dinv[node];

    uint2 sraw = __ldcg(&H2[(size_t)node * 32 + lane]);
    float2 s01 = __half22float2(*reinterpret_cast<const __half2*>(&sraw.x));
    float2 s23 = __half22float2(*reinterpret_cast<const __half2*>(&sraw.y));
    float4 acc = make_float4(s01.x * di, s01.y * di, s23.x * di, s23.y * di);

    int r0 = rowptr[node];
    int r1 = rowptr[node + 1];

    for (int base = r0; base < r1; base += 32) {
        int e   = base + lane;
        int2 eL = (e < r1) ? edge[e] : make_int2(0, 0);
        int cnt = min(32, r1 - base);

        int j = 0;
        for (; j + 8 <= cnt; j += 8) {
            uint2 v[8];
            float sc[8];
#pragma unroll
            for (int t = 0; t < 8; t++) {
                int src = __shfl_sync(0xffffffffu, eL.x, j + t);
                sc[t]   = __int_as_float(__shfl_sync(0xffffffffu, eL.y, j + t));
                v[t]    = __ldcg(&H2[(size_t)src * 32 + lane]);
            }
#pragma unroll
            for (int t = 0; t < 8; t++) {
                float2 f01 = __half22float2(*reinterpret_cast<const __half2*>(&v[t].x));
                float2 f23 = __half22float2(*reinterpret_cast<const __half2*>(&v[t].y));
                acc.x += f01.x * sc[t];
                acc.y += f01.y * sc[t];
                acc.z += f23.x * sc[t];
                acc.w += f23.y * sc[t];
            }
        }
        for (; j + 4 <= cnt; j += 4) {
            uint2 v[4];
            float sc[4];
#pragma unroll
            for (int t = 0; t < 4; t++) {
                int src = __shfl_sync(0xffffffffu, eL.x, j + t);
                sc[t]   = __int_as_float(__shfl_sync(0xffffffffu, eL.y, j + t));
                v[t]    = __ldcg(&H2[(size_t)src * 32 + lane]);
            }
#pragma unroll
            for (int t = 0; t < 4; t++) {
                float2 f01 = __half22float2(*reinterpret_cast<const __half2*>(&v[t].x));
                float2 f23 = __half22float2(*reinterpret_cast<const __half2*>(&v[t].y));
                acc.x += f01.x * sc[t];
                acc.y += f01.y * sc[t];
                acc.z += f23.x * sc[t];
                acc.w += f23.y * sc[t];
            }
        }
        for (; j < cnt; j++) {
            int   src = __shfl_sync(0xffffffffu, eL.x, j);
            float sc  = __int_as_float(__shfl_sync(0xffffffffu, eL.y, j));
            uint2 v   = __ldcg(&H2[(size_t)src * 32 + lane]);
            float2 f01 = __half22float2(*reinterpret_cast<const __half2*>(&v.x));
            float2 f23 = __half22float2(*reinterpret_cast<const __half2*>(&v.y));
            acc.x += f01.x * sc;
            acc.y += f01.y * sc;
            acc.z += f23.x * sc;
            acc.w += f23.y * sc;
        }
    }

    float4 bb = ((const float4*)b)[lane];
    float4 aa = ((const float4*)pa)[lane];
    float4 o;
    o.x = acc.x * di + bb.x;
    o.y = acc.y * di + bb.y;
    o.z = acc.z * di + bb.z;
    o.w = acc.w * di + bb.w;
    o.x = o.x > 0.f ? o.x : aa.x * o.x;
    o.y = o.y > 0.f ? o.y : aa.y * o.y;
    o.z = o.z > 0.f ? o.z : aa.z * o.z;
    o.w = o.w > 0.f ? o.w : aa.w * o.w;
    ((float4*)out)[(size_t)node * 32 + lane] = o;
}

// ---------------- launch ----------------
extern "C" void kernel_launch(void* const* d_in, const int* in_sizes, int n_in,
                              void* d_out, int out_size) {
    const float* x  = (const float*)d_in[0];
    const int*   ei = (const int*)d_in[1];     // [2, N_EDGES] int32
    const float* W  = (const float*)d_in[2];
    const float* b  = (const float*)d_in[3];
    const float* pa = (const float*)d_in[4];
    float* out = (float*)d_out;

    int*    deg;    cudaGetSymbolAddress((void**)&deg,    g_deg);
    float*  dinv;   cudaGetSymbolAddress((void**)&dinv,   g_dinv);
    int*    rowptr; cudaGetSymbolAddress((void**)&rowptr, g_rowptr);
    int*    cursor; cudaGetSymbolAddress((void**)&cursor, g_cursor);
    int2*   edge;   cudaGetSymbolAddress((void**)&edge,   g_edge);
    int*    bsum;   cudaGetSymbolAddress((void**)&bsum,   g_bsum);
    __half* h;      cudaGetSymbolAddress((void**)&h,      g_h);

    cudaEventRecord(g_evFork, 0);
    cudaStreamWaitEvent(g_s2, g_evFork, 0);

    // build chain on s2
    cudaMemsetAsync(deg, 0, N_NODES * sizeof(int), g_s2);
    cudaMemsetAsync(bsum, 0, 64 * sizeof(int), g_s2);
    k_count<<<(N_EDGES / 4 + 255) / 256, 256, 0, g_s2>>>(
        (const int4*)(ei + N_EDGES), deg);
    k_scanf<<<SCAN_BLOCKS, 256, 0, g_s2>>>(deg, bsum, rowptr, cursor, dinv);
    k_fill <<<(N_EDGES / 2 + 255) / 256, 256, 0, g_s2>>>(
        (const int2*)ei, (const int2*)(ei + N_EDGES), cursor, dinv, edge);
    cudaEventRecord(g_evJoin, g_s2);

    // GEMM on capture stream, no deps — overlaps entire build
    k_gemm16<<<(N_NODES + 63) / 64, 256>>>(x, W, h);

    cudaStreamWaitEvent(0, g_evJoin, 0);
    k_gather<<<(N_NODES + 7) / 8, 256>>>(rowptr, edge, dinv, h, b, pa, out);
}

// round 11
// speedup vs baseline: 1.4387x; 1.1199x over previous
#include <cuda_runtime.h>
#include <cuda_fp16.h>
#include <cstdint>

#define N_NODES 50000
#define N_EDGES 800000
#define D_IN    256
#define D_OUT   128

#define SCAN_BLOCKS ((N_NODES + 1023) / 1024)   // 49

// ---------------- scratch (no allocations allowed) ----------------
__device__ int    g_deg   [N_NODES];
__device__ float  g_dinv  [N_NODES];
__device__ int    g_rowptr[N_NODES + 1];
__device__ int    g_cursor[N_NODES];
__device__ int2   g_edge  [N_EDGES];     // {src, __float_as_int(dinv[src])}
__device__ int    g_bsum  [64];
__device__ __align__(16) __half g_h[(size_t)N_NODES * D_OUT];   // 12.8 MB

// ---------------- streams/events (created before capture) ----------------
static cudaStream_t g_s2;
static cudaEvent_t  g_evFork, g_evJoin;
static struct StreamInit {
    StreamInit() {
        cudaStreamCreateWithFlags(&g_s2, cudaStreamNonBlocking);
        cudaEventCreateWithFlags(&g_evFork, cudaEventDisableTiming);
        cudaEventCreateWithFlags(&g_evJoin, cudaEventDisableTiming);
    }
} g_streamInit;

// ---------------- 1. histogram of dst (x4 vectorized) ----------------
__global__ void k_count(const int4* __restrict__ dst4, int* deg) {
    int e = blockIdx.x * blockDim.x + threadIdx.x;
    if (e < N_EDGES / 4) {
        int4 d = dst4[e];
        atomicAdd(&deg[d.x], 1);
        atomicAdd(&deg[d.y], 1);
        atomicAdd(&deg[d.z], 1);
        atomicAdd(&deg[d.w], 1);
    }
}

// ---------------- 2. fused scan: decoupled lookback (49 co-resident blocks) -
__global__ __launch_bounds__(256) void k_scanf(const int* __restrict__ deg,
                                               int* bsum,     // zeroed, publish s+1
                                               int* __restrict__ rowptr,
                                               int* __restrict__ cursor,
                                               float* __restrict__ dinv) {
    __shared__ int ws[8];
    __shared__ int woff[8];
    __shared__ int pred[64];
    __shared__ int boffs;

    int b = blockIdx.x, t = threadIdx.x;
    int lane = t & 31, w = t >> 5;
    int base = b * 1024 + t * 4;

    int d[4];
    int s = 0;
#pragma unroll
    for (int q = 0; q < 4; q++) {
        int i = base + q;
        d[q] = (i < N_NODES) ? deg[i] : 0;
        s += d[q];
    }
    int inc = s;
    for (int o = 1; o < 32; o <<= 1) {
        int v = __shfl_up_sync(0xffffffffu, inc, o);
        if (lane >= o) inc += v;
    }
    if (lane == 31) ws[w] = inc;
    if (t < 64) pred[t] = 0;
    __syncthreads();

    if (t < 8) {
        int v = ws[t];
        int p = v;
        for (int o = 1; o < 8; o <<= 1) {
            int u = __shfl_up_sync(0xffu, p, o);
            if (t >= o) p += u;
        }
        woff[t] = p - v;
        if (t == 7) {
            __threadfence();
            atomicExch(&bsum[b], p + 1);
        }
    }
    if (t < b) {
        int v;
        do { v = *((volatile int*)&bsum[t]); } while (v == 0);
        pred[t] = v - 1;
    }
    __syncthreads();
    if (t < 32) {
        int ss = pred[t] + pred[t + 32];
        for (int o = 16; o; o >>= 1) ss += __shfl_down_sync(0xffffffffu, ss, o);
        if (t == 0) boffs = ss;
    }
    __syncthreads();

    int off = boffs + woff[w] + (inc - s);
#pragma unroll
    for (int q = 0; q < 4; q++) {
        int i = base + q;
        if (i < N_NODES) {
            rowptr[i] = off;
            cursor[i] = off;
            dinv[i]   = rsqrtf((float)d[q] + 1.0f);   // +1 = self loop
            off += d[q];
        }
    }
    if (b == 0 && t == 0) rowptr[N_NODES] = N_EDGES;
}

// ---------------- 3. bucket fill x2: {src, dinv[src]} ----------------
__global__ void k_fill(const int2* __restrict__ src2,
                       const int2* __restrict__ dst2,
                       int* __restrict__ cursor,
                       const float* __restrict__ dinv,
                       int2* __restrict__ edge) {
    int e = blockIdx.x * blockDim.x + threadIdx.x;
    if (e < N_EDGES / 2) {
        int2 s = src2[e];
        int2 d = dst2[e];
        float f0 = dinv[s.x];
        float f1 = dinv[s.y];
        int p0 = atomicAdd(&cursor[d.x], 1);
        edge[p0] = make_int2(s.x, __float_as_int(f0));
        int p1 = atomicAdd(&cursor[d.y], 1);
        edge[p1] = make_int2(s.y, __float_as_int(f1));
    }
}

// ---------------- 4. GEMM h = x @ W, fp16 mma.sync, streaming A+B ----------
// block tile 64x128, 8 warps as 4(m) x 2(n); warp tile m16 n64.
// smem per stage: A 64x16 half (stride 24), B 8 k-pairs x 132 half2. ~20 KB.
#define AS_STRIDE 24
#define AS_STAGE  (64 * AS_STRIDE)      // halves
#define BS_STAGE  (8 * 132)             // half2

__global__ __launch_bounds__(256, 4) void k_gemm16(const float* __restrict__ X,
                                                   const float* __restrict__ W,
                                                   __half* __restrict__ H) {
    __shared__ __half As[2][AS_STAGE];
    __shared__ half2  Bs[2][BS_STAGE];

    const int tid  = threadIdx.x;
    const int warp = tid >> 5;
    const int lane = tid & 31;
    const int g    = lane >> 2;      // 0..7
    const int tig  = lane & 3;       // 0..3
    const int m0   = blockIdx.x * 64;
    const int mrow = (warp >> 1) * 16;   // 0,16,32,48
    const int ncol = (warp & 1) * 64;    // 0 or 64

    const float4* X4 = (const float4*)X;   // row stride 64
    const float4* W4 = (const float4*)W;   // row stride 32

    // per-chunk loader indices
    const int ar  = tid >> 2;        // 0..63  A row
    const int ac4 = tid & 3;         // 0..3   A k-quad (4 floats)
    const int bkp = tid >> 5;        // 0..7   B k-pair row
    const int bn4 = tid & 31;        // 0..31  B float4 col

    // ---- stage 0
    {
        int gr = m0 + ar;
        float4 v = make_float4(0.f, 0.f, 0.f, 0.f);
        if (gr < N_NODES) v = X4[(size_t)gr * 64 + ac4];
        half2 h01 = __floats2half2_rn(v.x, v.y);
        half2 h23 = __floats2half2_rn(v.z, v.w);
        uint2 u; u.x = *(unsigned*)&h01; u.y = *(unsigned*)&h23;
        *(uint2*)(&As[0][ar * AS_STRIDE + ac4 * 4]) = u;

        float4 a = W4[(size_t)(2 * bkp) * 32 + bn4];
        float4 c = W4[(size_t)(2 * bkp + 1) * 32 + bn4];
        half2 p0 = __floats2half2_rn(a.x, c.x);
        half2 p1 = __floats2half2_rn(a.y, c.y);
        half2 p2 = __floats2half2_rn(a.z, c.z);
        half2 p3 = __floats2half2_rn(a.w, c.w);
        uint4 pk;
        pk.x = *(unsigned*)&p0; pk.y = *(unsigned*)&p1;
        pk.z = *(unsigned*)&p2; pk.w = *(unsigned*)&p3;
        *(uint4*)(&Bs[0][bkp * 132 + bn4 * 4]) = pk;
    }
    __syncthreads();

    float acc[8][4];
#pragma unroll
    for (int nt = 0; nt < 8; nt++)
#pragma unroll
        for (int j = 0; j < 4; j++) acc[nt][j] = 0.0f;

    int buf = 0;
#pragma unroll 1
    for (int ks = 0; ks < 16; ks++) {
        // reg-prefetch next chunk
        float4 preA = make_float4(0.f, 0.f, 0.f, 0.f);
        float4 preB0, preB1;
        if (ks + 1 < 16) {
            int k0n = (ks + 1) * 16;
            int gr = m0 + ar;
            if (gr < N_NODES) preA = X4[(size_t)gr * 64 + (k0n >> 2) + ac4];
            preB0 = W4[(size_t)(k0n + 2 * bkp) * 32 + bn4];
            preB1 = W4[(size_t)(k0n + 2 * bkp + 1) * 32 + bn4];
        }

        // A fragment (m16 k16) for this warp
        const __half* Ab = &As[buf][0];
        int r = mrow + g;
        unsigned a0 = *(const unsigned*)(Ab + r * AS_STRIDE + 2 * tig);
        unsigned a1 = *(const unsigned*)(Ab + (r + 8) * AS_STRIDE + 2 * tig);
        unsigned a2 = *(const unsigned*)(Ab + r * AS_STRIDE + 2 * tig + 8);
        unsigned a3 = *(const unsigned*)(Ab + (r + 8) * AS_STRIDE + 2 * tig + 8);

#pragma unroll
        for (int nt = 0; nt < 8; nt++) {
            int n0 = ncol + nt * 8;
            unsigned b0 = *(const unsigned*)&Bs[buf][tig * 132 + n0 + g];
            unsigned b1 = *(const unsigned*)&Bs[buf][(tig + 4) * 132 + n0 + g];
            asm volatile(
                "mma.sync.aligned.m16n8k16.row.col.f32.f16.f16.f32 "
                "{%0,%1,%2,%3}, {%4,%5,%6,%7}, {%8,%9}, {%0,%1,%2,%3};\n"
                : "+f"(acc[nt][0]), "+f"(acc[nt][1]),
                  "+f"(acc[nt][2]), "+f"(acc[nt][3])
                : "r"(a0), "r"(a1), "r"(a2), "r"(a3), "r"(b0), "r"(b1));
        }

        if (ks + 1 < 16) {
            int nbuf = buf ^ 1;
            half2 h01 = __floats2half2_rn(preA.x, preA.y);
            half2 h23 = __floats2half2_rn(preA.z, preA.w);
            uint2 u; u.x = *(unsigned*)&h01; u.y = *(unsigned*)&h23;
            *(uint2*)(&As[nbuf][ar * AS_STRIDE + ac4 * 4]) = u;

            half2 p0 = __floats2half2_rn(preB0.x, preB1.x);
            half2 p1 = __floats2half2_rn(preB0.y, preB1.y);
            half2 p2 = __floats2half2_rn(preB0.z, preB1.z);
            half2 p3 = __floats2half2_rn(preB0.w, preB1.w);
            uint4 pk;
            pk.x = *(unsigned*)&p0; pk.y = *(unsigned*)&p1;
            pk.z = *(unsigned*)&p2; pk.w = *(unsigned*)&p3;
            *(uint4*)(&Bs[nbuf][bkp * 132 + bn4 * 4]) = pk;
            __syncthreads();
            buf = nbuf;
        }
    }

    // ---- epilogue: fp32 acc -> fp16 H (unscaled)
    int r0 = m0 + mrow + g;
#pragma unroll
    for (int nt = 0; nt < 8; nt++) {
        int col = ncol + nt * 8 + 2 * tig;
        half2 lo = __floats2half2_rn(acc[nt][0], acc[nt][1]);
        half2 hi = __floats2half2_rn(acc[nt][2], acc[nt][3]);
        if (r0 < N_NODES)
            *(unsigned*)(H + (size_t)r0 * 128 + col) = *(unsigned*)&lo;
        if (r0 + 8 < N_NODES)
            *(unsigned*)(H + (size_t)(r0 + 8) * 128 + col) = *(unsigned*)&hi;
    }
}

// ---------------- 5. gather (fp16 rows) + self-loop + bias + PReLU ----------
__global__ __launch_bounds__(256) void k_gather(const int* __restrict__ rowptr,
                                                const int2* __restrict__ edge,
                                                const float* __restrict__ dinv,
                                                const __half* __restrict__ H,
                                                const float* __restrict__ b,
                                                const float* __restrict__ pa,
                                                float* __restrict__ out) {
    int node = blockIdx.x * 8 + (threadIdx.x >> 5);
    int lane = threadIdx.x & 31;
    if (node >= N_NODES) return;

    const uint2* H2 = (const uint2*)H;
    float di = dinv[node];

    uint2 sraw = __ldcg(&H2[(size_t)node * 32 + lane]);
    float2 s01 = __half22float2(*reinterpret_cast<const __half2*>(&sraw.x));
    float2 s23 = __half22float2(*reinterpret_cast<const __half2*>(&sraw.y));
    float4 acc = make_float4(s01.x * di, s01.y * di, s23.x * di, s23.y * di);

    int r0 = rowptr[node];
    int r1 = rowptr[node + 1];

    for (int base = r0; base < r1; base += 32) {
        int e   = base + lane;
        int2 eL = (e < r1) ? edge[e] : make_int2(0, 0);
        int cnt = min(32, r1 - base);

        int j = 0;
        for (; j + 8 <= cnt; j += 8) {
            uint2 v[8];
            float sc[8];
#pragma unroll
            for (int t = 0; t < 8; t++) {
                int src = __shfl_sync(0xffffffffu, eL.x, j + t);
                sc[t]   = __int_as_float(__shfl_sync(0xffffffffu, eL.y, j + t));
                v[t]    = __ldcg(&H2[(size_t)src * 32 + lane]);
            }
#pragma unroll
            for (int t = 0; t < 8; t++) {
                float2 f01 = __half22float2(*reinterpret_cast<const __half2*>(&v[t].x));
                float2 f23 = __half22float2(*reinterpret_cast<const __half2*>(&v[t].y));
                acc.x += f01.x * sc[t];
                acc.y += f01.y * sc[t];
                acc.z += f23.x * sc[t];
                acc.w += f23.y * sc[t];
            }
        }
        for (; j + 4 <= cnt; j += 4) {
            uint2 v[4];
            float sc[4];
#pragma unroll
            for (int t = 0; t < 4; t++) {
                int src = __shfl_sync(0xffffffffu, eL.x, j + t);
                sc[t]   = __int_as_float(__shfl_sync(0xffffffffu, eL.y, j + t));
                v[t]    = __ldcg(&H2[(size_t)src * 32 + lane]);
            }
#pragma unroll
            for (int t = 0; t < 4; t++) {
                float2 f01 = __half22float2(*reinterpret_cast<const __half2*>(&v[t].x));
                float2 f23 = __half22float2(*reinterpret_cast<const __half2*>(&v[t].y));
                acc.x += f01.x * sc[t];
                acc.y += f01.y * sc[t];
                acc.z += f23.x * sc[t];
                acc.w += f23.y * sc[t];
            }
        }
        for (; j < cnt; j++) {
            int   src = __shfl_sync(0xffffffffu, eL.x, j);
            float sc  = __int_as_float(__shfl_sync(0xffffffffu, eL.y, j));
            uint2 v   = __ldcg(&H2[(size_t)src * 32 + lane]);
            float2 f01 = __half22float2(*reinterpret_cast<const __half2*>(&v.x));
            float2 f23 = __half22float2(*reinterpret_cast<const __half2*>(&v.y));
            acc.x += f01.x * sc;
            acc.y += f01.y * sc;
            acc.z += f23.x * sc;
            acc.w += f23.y * sc;
        }
    }

    float4 bb = ((const float4*)b)[lane];
    float4 aa = ((const float4*)pa)[lane];
    float4 o;
    o.x = acc.x * di + bb.x;
    o.y = acc.y * di + bb.y;
    o.z = acc.z * di + bb.z;
    o.w = acc.w * di + bb.w;
    o.x = o.x > 0.f ? o.x : aa.x * o.x;
    o.y = o.y > 0.f ? o.y : aa.y * o.y;
    o.z = o.z > 0.f ? o.z : aa.z * o.z;
    o.w = o.w > 0.f ? o.w : aa.w * o.w;
    ((float4*)out)[(size_t)node * 32 + lane] = o;
}

// ---------------- launch ----------------
extern "C" void kernel_launch(void* const* d_in, const int* in_sizes, int n_in,
                              void* d_out, int out_size) {
    const float* x  = (const float*)d_in[0];
    const int*   ei = (const int*)d_in[1];     // [2, N_EDGES] int32
    const float* W  = (const float*)d_in[2];
    const float* b  = (const float*)d_in[3];
    const float* pa = (const float*)d_in[4];
    float* out = (float*)d_out;

    int*    deg;    cudaGetSymbolAddress((void**)&deg,    g_deg);
    float*  dinv;   cudaGetSymbolAddress((void**)&dinv,   g_dinv);
    int*    rowptr; cudaGetSymbolAddress((void**)&rowptr, g_rowptr);
    int*    cursor; cudaGetSymbolAddress((void**)&cursor, g_cursor);
    int2*   edge;   cudaGetSymbolAddress((void**)&edge,   g_edge);
    int*    bsum;   cudaGetSymbolAddress((void**)&bsum,   g_bsum);
    __half* h;      cudaGetSymbolAddress((void**)&h,      g_h);

    cudaEventRecord(g_evFork, 0);
    cudaStreamWaitEvent(g_s2, g_evFork, 0);

    // build chain on s2
    cudaMemsetAsync(deg, 0, N_NODES * sizeof(int), g_s2);
    cudaMemsetAsync(bsum, 0, 64 * sizeof(int), g_s2);
    k_count<<<(N_EDGES / 4 + 255) / 256, 256, 0, g_s2>>>(
        (const int4*)(ei + N_EDGES), deg);
    k_scanf<<<SCAN_BLOCKS, 256, 0, g_s2>>>(deg, bsum, rowptr, cursor, dinv);
    k_fill <<<(N_EDGES / 2 + 255) / 256, 256, 0, g_s2>>>(
        (const int2*)ei, (const int2*)(ei + N_EDGES), cursor, dinv, edge);
    cudaEventRecord(g_evJoin, g_s2);

    // GEMM on capture stream, no deps — overlaps entire build
    k_gemm16<<<(N_NODES + 63) / 64, 256>>>(x, W, h);

    cudaStreamWaitEvent(0, g_evJoin, 0);
    k_gather<<<(N_NODES + 7) / 8, 256>>>(rowptr, edge, dinv, h, b, pa, out);
}